// round 14
// baseline (speedup 1.0000x reference)
#include <cuda_runtime.h>
#include <cuda_bf16.h>
#include <cstdint>
#include <math.h>

// ---------------------------------------------------------------------------
// CustomLSTM: 2-layer LSTM, B=128, T=256, F=H=1024.
// Round 14:
//   * tcgen05 scan: 3 -> 4 smem stages (192KB); stage-reuse wait moved from
//     chunk g-1 to g-2 (slack for MMA completion latency); 4 mbarriers (one
//     per stage) so parity aliasing is impossible at the deeper depth.
//   * Prep kernels fused 4 -> 2 so the run has exactly 4 launches and the
//     fixed ncu window (-s 5 -c 1, lands on my 4th launch) captures k_scan.
//   * Dual-target build kept: tcgen05 on arch-specific pass, mma.sync
//     fallback on the plain sm_103 pass.
// ---------------------------------------------------------------------------

#define DI __device__ __forceinline__

// tcgen05 available only in arch-specific device passes (sm_103a etc.)
#if defined(__CUDA_ARCH__) && !(defined(__CUDA_ARCH_FEAT_SM103_ALL) ||       \
    defined(__CUDA_ARCH_FEAT_SM100_ALL) || defined(__CUDA_ARCH_SPECIFIC__) ||\
    defined(__CUDA_ARCH_FAMILY_SPECIFIC__))
#define T5_OK 0
#else
#define T5_OK 1
#endif

constexpr int BATCH = 128;
constexpr int SEQ   = 256;
constexpr int FDIM  = 1024;
constexpr int HDIM  = 1024;
constexpr int G4    = 4096;          // 4*H
constexpr int KS    = 2048;          // compact split width [hi|lo]
constexpr int MTOT  = BATCH * SEQ;   // 32768
constexpr int NCTA  = 64;            // persistent scan CTAs
constexpr int SSTR  = 72;            // smem row stride for mma.sync paths

// scan smem stage layout (bytes) for tcgen05 path
constexpr int STG_AH = 0;            // 128 rows x 128B
constexpr int STG_AL = 16384;
constexpr int STG_BH = 32768;        // 64 rows x 128B
constexpr int STG_BL = 40960;
constexpr int STG_SZ = 49152;        // 48KB per stage
constexpr int NSTG   = 4;
constexpr int SCAN_DYN = NSTG * STG_SZ + 1024;   // 197632 (covers fallback too)

// idesc kind::f16: F32 acc, bf16 a/b, N=64, M=128
constexpr uint32_t IDESC_F16 =
    (1u << 4) | (1u << 7) | (1u << 10) | ((64u / 8) << 17) | ((128u / 16) << 24);

// SW128 smem descriptor base (Blackwell): layout=SW128, ver=1, SBO=64, LBO=1
constexpr uint64_t DESC_SW128 =
    (uint64_t(2) << 61) | (uint64_t(1) << 46) | (uint64_t(64) << 32) | (uint64_t(1) << 16);
#define MK_DESC(addr) (DESC_SW128 | ((uint64_t)((addr) >> 4) & 0x3FFF))

// ------------------------- device scratch (globals) ------------------------
__device__ __nv_bfloat16 g_Wih0s[(size_t)G4 * KS];
__device__ __nv_bfloat16 g_Whh0s[(size_t)G4 * KS];
__device__ __nv_bfloat16 g_Wih1s[(size_t)G4 * KS];
__device__ __nv_bfloat16 g_Whh1s[(size_t)G4 * KS];
__device__ __nv_bfloat16 g_xs[(size_t)MTOT * KS];             // split x [hi|lo]
__device__ float         g_gates_x[(size_t)SEQ * BATCH * G4]; // [t][b][c] permuted
__device__ __nv_bfloat16 g_h0s[2][(size_t)BATCH * KS];        // double-buffered
__device__ __nv_bfloat16 g_h1s[2][(size_t)BATCH * KS];
__device__ float         g_bias0[G4];   // permuted
__device__ float         g_bias1[G4];   // permuted

__device__ unsigned g_bar_cnt;
__device__ unsigned g_bar_gen;

// ------------------------------ small helpers ------------------------------
DI float sigf(float x) { return 1.0f / (1.0f + __expf(-x)); }

DI int gate_perm(int n) {            // row n -> permuted col
    int g = n >> 10, j = n & 1023;
    return ((j >> 4) << 6) + (g << 4) + (j & 15);
}

DI uint32_t smem_u32(const void* p) {
    uint32_t a;
    asm("{ .reg .u64 t; cvta.to.shared.u64 t, %1; cvt.u32.u64 %0, t; }"
        : "=r"(a) : "l"(p));
    return a;
}

DI uint32_t elect1() {
    uint32_t p;
    asm volatile("{\n\t.reg .pred p;\n\telect.sync _|p, 0xFFFFFFFF;\n\t"
                 "selp.b32 %0, 1, 0, p;\n\t}" : "=r"(p));
    return p;
}

DI void ldsm4(uint32_t* r, const __nv_bfloat16* p) {
    uint32_t a = (uint32_t)__cvta_generic_to_shared(p);
    asm volatile("ldmatrix.sync.aligned.m8n8.x4.shared.b16 {%0,%1,%2,%3}, [%4];"
                 : "=r"(r[0]), "=r"(r[1]), "=r"(r[2]), "=r"(r[3]) : "r"(a));
}

DI void mma16816(float* d, const uint32_t* a, uint32_t b0, uint32_t b1) {
    asm volatile(
        "mma.sync.aligned.m16n8k16.row.col.f32.bf16.bf16.f32 "
        "{%0,%1,%2,%3}, {%4,%5,%6,%7}, {%8,%9}, {%0,%1,%2,%3};"
        : "+f"(d[0]), "+f"(d[1]), "+f"(d[2]), "+f"(d[3])
        : "r"(a[0]), "r"(a[1]), "r"(a[2]), "r"(a[3]), "r"(b0), "r"(b1));
}

DI void cp16(void* dst, const void* src) {
    uint32_t d = (uint32_t)__cvta_generic_to_shared(dst);
    asm volatile("cp.async.cg.shared.global [%0], [%1], 16;\n" :: "r"(d), "l"(src));
}
DI void cp16s(uint32_t dst, const void* src) {
    asm volatile("cp.async.cg.shared.global [%0], [%1], 16;\n" :: "r"(dst), "l"(src));
}
DI void cp_commit() { asm volatile("cp.async.commit_group;\n" ::: "memory"); }
DI void cp_wait1()  { asm volatile("cp.async.wait_group 1;\n"  ::: "memory"); }
DI void cp_wait2()  { asm volatile("cp.async.wait_group 2;\n"  ::: "memory"); }

DI void grid_bar() {
    __syncthreads();
    if (threadIdx.x == 0) {
        unsigned gen = *(volatile unsigned*)&g_bar_gen;
        __threadfence();
        if (atomicAdd(&g_bar_cnt, 1u) == NCTA - 1u) {
            atomicExch(&g_bar_cnt, 0u);
            __threadfence();
            atomicExch(&g_bar_gen, gen + 1u);
        } else {
            while (*(volatile unsigned*)&g_bar_gen == gen) { __nanosleep(32); }
        }
        __threadfence();
    }
    __syncthreads();
}

// ---------------------------- tcgen05 wrappers ------------------------------
#if T5_OK
#define T5_ALLOC(smem_addr, n) \
    asm volatile("tcgen05.alloc.cta_group::1.sync.aligned.shared::cta.b32 [%0], %1;" \
                 :: "r"(smem_addr), "r"((uint32_t)(n)) : "memory")
#define T5_DEALLOC(tmem, n) \
    asm volatile("tcgen05.dealloc.cta_group::1.sync.aligned.b32 %0, %1;" \
                 :: "r"(tmem), "r"((uint32_t)(n)))
#define T5_RELINQ() \
    asm volatile("tcgen05.relinquish_alloc_permit.cta_group::1.sync.aligned;")
#define T5_COMMIT(mb) \
    asm volatile("tcgen05.commit.cta_group::1.mbarrier::arrive::one.shared::cluster.b64 [%0];" \
                 :: "r"(mb) : "memory")
#define T5_FENCE_AFTER()  asm volatile("tcgen05.fence::after_thread_sync;" ::: "memory")
#define T5_FENCE_BEFORE() asm volatile("tcgen05.fence::before_thread_sync;" ::: "memory")
#define T5_WAIT_LD()      asm volatile("tcgen05.wait::ld.sync.aligned;" ::: "memory")

#define MBAR_INIT(mb, cnt) \
    asm volatile("mbarrier.init.shared.b64 [%0], %1;" :: "r"(mb), "r"((uint32_t)(cnt)) : "memory")

#define MBAR_WAIT(mb, par) do {                                              \
    uint32_t _mb = (mb), _pp = (par), _done;                                 \
    asm volatile("{\n\t.reg .pred p;\n\t"                                    \
        "mbarrier.try_wait.parity.acquire.cta.shared::cta.b64 p, [%1], %2;\n\t" \
        "selp.b32 %0, 1, 0, p;\n\t}" : "=r"(_done) : "r"(_mb), "r"(_pp) : "memory"); \
    if (!_done) {                                                            \
        asm volatile("{\n\t.reg .pred P1;\n\t"                               \
            "WL_%=:\n\t"                                                     \
            "mbarrier.try_wait.parity.acquire.cta.shared::cta.b64 P1, [%0], %1, 0x989680;\n\t" \
            "@P1 bra.uni WD_%=;\n\t"                                         \
            "bra.uni WL_%=;\n\t"                                             \
            "WD_%=:\n\t}" :: "r"(_mb), "r"(_pp) : "memory");                 \
    }                                                                        \
} while (0)

#define T5_LD_X32(r, tm)                                                     \
    asm volatile("tcgen05.ld.sync.aligned.32x32b.x32.b32 "                   \
        "{%0, %1, %2, %3, %4, %5, %6, %7, "                                  \
        " %8, %9, %10, %11, %12, %13, %14, %15, "                            \
        " %16, %17, %18, %19, %20, %21, %22, %23, "                          \
        " %24, %25, %26, %27, %28, %29, %30, %31}, [%32];"                   \
        : "=r"((r)[0]),  "=r"((r)[1]),  "=r"((r)[2]),  "=r"((r)[3]),         \
          "=r"((r)[4]),  "=r"((r)[5]),  "=r"((r)[6]),  "=r"((r)[7]),         \
          "=r"((r)[8]),  "=r"((r)[9]),  "=r"((r)[10]), "=r"((r)[11]),        \
          "=r"((r)[12]), "=r"((r)[13]), "=r"((r)[14]), "=r"((r)[15]),        \
          "=r"((r)[16]), "=r"((r)[17]), "=r"((r)[18]), "=r"((r)[19]),        \
          "=r"((r)[20]), "=r"((r)[21]), "=r"((r)[22]), "=r"((r)[23]),        \
          "=r"((r)[24]), "=r"((r)[25]), "=r"((r)[26]), "=r"((r)[27]),        \
          "=r"((r)[28]), "=r"((r)[29]), "=r"((r)[30]), "=r"((r)[31])         \
        : "r"(tm))

DI void mma_f16_ss(uint32_t d, uint64_t a, uint64_t b, uint32_t en) {
    asm volatile(
        "{\n\t.reg .pred p;\n\tsetp.ne.u32 p, %4, 0;\n\t"
        "tcgen05.mma.cta_group::1.kind::f16 [%0], %1, %2, %3, {%5,%5,%5,%5}, p;\n\t}"
        :: "r"(d), "l"(a), "l"(b), "r"(IDESC_F16), "r"(en), "r"(0u) : "memory");
}
#endif  // T5_OK

// ----------------------- fused prep kernels (2 launches) --------------------
__global__ void k_prep_w(const float* __restrict__ W0, const float* __restrict__ W1,
                         const float* __restrict__ W2, const float* __restrict__ W3,
                         const float* __restrict__ b_ih0, const float* __restrict__ b_hh0,
                         const float* __restrict__ b_ih1, const float* __restrict__ b_hh1) {
    size_t idx = (size_t)blockIdx.x * blockDim.x + threadIdx.x;
    if (idx < (size_t)G4) {                        // fused bias prep
        int i = (int)idx;
        int c = gate_perm(i);
        g_bias0[c] = b_ih0[i] + b_hh0[i];
        g_bias1[c] = b_ih1[i] + b_hh1[i];
    }
    if (idx >= (size_t)4 * G4 * FDIM) return;
    int which = (int)(idx >> 22);
    int r = (int)(idx & 4194303);
    const float* W = which == 0 ? W0 : which == 1 ? W1 : which == 2 ? W2 : W3;
    __nv_bfloat16* Ws = which == 0 ? g_Wih0s : which == 1 ? g_Whh0s
                       : which == 2 ? g_Wih1s : g_Whh1s;
    int n = r >> 10, k = r & 1023;
    int c = gate_perm(n);
    float v = W[r];
    __nv_bfloat16 hi = __float2bfloat16(v);
    __nv_bfloat16 lo = __float2bfloat16(v - __bfloat162float(hi));
    __nv_bfloat16* row = Ws + (size_t)c * KS;
    row[k] = hi; row[1024 + k] = lo;
}

__global__ void k_prep_x(const float* __restrict__ x) {
    size_t idx = (size_t)blockIdx.x * blockDim.x + threadIdx.x;
    if (idx < (size_t)BATCH * KS) {                // fused h-state init
        __nv_bfloat16 z = __float2bfloat16(0.0f);
        g_h0s[0][idx] = z; g_h1s[0][idx] = z;
    }
    if (idx >= (size_t)MTOT * FDIM) return;
    int m = (int)(idx >> 10), k = (int)(idx & 1023);
    float v = x[idx];
    __nv_bfloat16 hi = __float2bfloat16(v);
    __nv_bfloat16 lo = __float2bfloat16(v - __bfloat162float(hi));
    __nv_bfloat16* row = g_xs + (size_t)m * KS;
    row[k] = hi; row[1024 + k] = lo;
}

// ------------- mma.sync cp.async 4-stage pipeline (pre-GEMM + fallback) -----
template <int BM, int BN, int WR, int WC, int NTH>
DI void gemm_cp(const __nv_bfloat16* __restrict__ A0,
                const __nv_bfloat16* __restrict__ B0,
                float* acc, __nv_bfloat16* sA, __nv_bfloat16* sB) {
    constexpr int WTM = BM / WR, WTN = BN / WC;
    constexpr int MT = WTM / 16, NG = WTN / 16;
    constexpr int AV = BM * 8 / NTH, BV = BN * 8 / NTH;
    constexpr int NITER = 32;
    constexpr int SZA = BM * SSTR, SZB = BN * SSTR;
    const int tid = threadIdx.x;
    const int warp = tid >> 5, lane = tid & 31;
    const int wm = warp % WR, wn = warp / WR;
    const int lr = lane & 15, lc = (lane >> 4) << 3;

    auto fetch = [&](int c, int st) {
        int k32 = c << 5;
#pragma unroll
        for (int i = 0; i < AV; i++) {
            int v = tid + i * NTH;
            int row = v >> 3, rem = v & 7, hf = rem >> 2, cp = (rem & 3) << 3;
            cp16(sA + st * SZA + row * SSTR + (hf << 5) + cp,
                 A0 + (size_t)row * KS + hf * 1024 + k32 + cp);
        }
#pragma unroll
        for (int i = 0; i < BV; i++) {
            int v = tid + i * NTH;
            int row = v >> 3, rem = v & 7, hf = rem >> 2, cp = (rem & 3) << 3;
            cp16(sB + st * SZB + row * SSTR + (hf << 5) + cp,
                 B0 + (size_t)row * KS + hf * 1024 + k32 + cp);
        }
        cp_commit();
    };

#pragma unroll
    for (int s = 0; s < 3; s++) fetch(s, s);

    for (int it = 0; it < NITER; it++) {
        cp_wait2();
        __syncthreads();
        if (it + 3 < NITER) fetch(it + 3, (it + 3) & 3);
        else cp_commit();
        const __nv_bfloat16* cA = sA + (it & 3) * SZA;
        const __nv_bfloat16* cB = sB + (it & 3) * SZB;
#pragma unroll
        for (int kk = 0; kk < 32; kk += 16) {
            uint32_t rah[MT][4], ral[MT][4], rbh[NG][4], rbl[NG][4];
#pragma unroll
            for (int mi = 0; mi < MT; mi++) {
                const __nv_bfloat16* p = cA + (wm * WTM + mi * 16 + lr) * SSTR + kk + lc;
                ldsm4(rah[mi], p);
                ldsm4(ral[mi], p + 32);
            }
#pragma unroll
            for (int ng = 0; ng < NG; ng++) {
                const __nv_bfloat16* p = cB + (wn * WTN + ng * 16 + lr) * SSTR + kk + lc;
                ldsm4(rbh[ng], p);
                ldsm4(rbl[ng], p + 32);
            }
#pragma unroll
            for (int mi = 0; mi < MT; mi++)
#pragma unroll
                for (int ng = 0; ng < NG; ng++) {
                    float* a0 = acc + ((mi * 2 * NG) + 2 * ng) * 4;
                    float* a1 = a0 + 4;
                    mma16816(a0, rah[mi], rbh[ng][0], rbh[ng][2]);
                    mma16816(a1, rah[mi], rbh[ng][1], rbh[ng][3]);
                    mma16816(a0, rah[mi], rbl[ng][0], rbl[ng][2]);
                    mma16816(a1, rah[mi], rbl[ng][1], rbl[ng][3]);
                    mma16816(a0, ral[mi], rbh[ng][0], rbh[ng][2]);
                    mma16816(a1, ral[mi], rbh[ng][1], rbh[ng][3]);
                }
        }
    }
}

constexpr int PRE_SMEM = 4 * (128 + 128) * SSTR * (int)sizeof(__nv_bfloat16);

__global__ void __launch_bounds__(256) k_gemm_pre() {
    extern __shared__ __nv_bfloat16 smem[];
    __nv_bfloat16* sA = smem;
    __nv_bfloat16* sB = smem + 4 * 128 * SSTR;
    const int m0 = blockIdx.y * 128, n0 = blockIdx.x * 128;
    float acc[64];
#pragma unroll
    for (int i = 0; i < 64; i++) acc[i] = 0.0f;

    gemm_cp<128, 128, 2, 4, 256>(g_xs + (size_t)m0 * KS,
                                 g_Wih0s + (size_t)n0 * KS, acc, sA, sB);

    const int lane = threadIdx.x & 31, warp = threadIdx.x >> 5;
    const int wm = warp & 1, wn = warp >> 1;
#pragma unroll
    for (int mi = 0; mi < 4; mi++)
#pragma unroll
        for (int ng = 0; ng < 2; ng++)
#pragma unroll
            for (int hf = 0; hf < 2; hf++) {
                const float* a4 = acc + ((mi * 4) + 2 * ng + hf) * 4;
                int r = m0 + wm * 64 + mi * 16 + (lane >> 2);
                int c = n0 + wn * 32 + ng * 16 + hf * 8 + ((lane & 3) << 1);
                {
                    int b = r >> 8, t = r & 255;
                    size_t d = (size_t)(t * BATCH + b) * G4 + c;
                    g_gates_x[d]     = a4[0] + g_bias0[c];
                    g_gates_x[d + 1] = a4[1] + g_bias0[c + 1];
                }
                {
                    int r2 = r + 8;
                    int b = r2 >> 8, t = r2 & 255;
                    size_t d = (size_t)(t * BATCH + b) * G4 + c;
                    g_gates_x[d]     = a4[2] + g_bias0[c];
                    g_gates_x[d + 1] = a4[3] + g_bias0[c + 1];
                }
            }
}

// -------------------------- scan: tcgen05 pieces ----------------------------
#if T5_OK
// Load one 64-col K-chunk (Ah/Al 128 rows, Bh/Bl 64 rows) into stage `st`.
DI void load_chunk(uint32_t st, const __nv_bfloat16* __restrict__ A,
                   const __nv_bfloat16* __restrict__ B, int kc, int tid) {
    const int kb = kc << 6;   // bf16 col base
#pragma unroll
    for (int i = 0; i < 24; i++) {
        int v = tid + (i << 7);
        uint32_t dst; const __nv_bfloat16* src;
        if (v < 1024) {
            int row = v >> 3, c = v & 7;
            uint32_t off = (uint32_t)(row * 128 + c * 16);
            dst = st + STG_AH + (off ^ ((off >> 3) & 0x70));
            src = A + (size_t)row * KS + kb + c * 8;
        } else if (v < 2048) {
            int w = v - 1024, row = w >> 3, c = w & 7;
            uint32_t off = (uint32_t)(row * 128 + c * 16);
            dst = st + STG_AL + (off ^ ((off >> 3) & 0x70));
            src = A + (size_t)row * KS + 1024 + kb + c * 8;
        } else if (v < 2560) {
            int w = v - 2048, row = w >> 3, c = w & 7;
            uint32_t off = (uint32_t)(row * 128 + c * 16);
            dst = st + STG_BH + (off ^ ((off >> 3) & 0x70));
            src = B + (size_t)row * KS + kb + c * 8;
        } else {
            int w = v - 2560, row = w >> 3, c = w & 7;
            uint32_t off = (uint32_t)(row * 128 + c * 16);
            dst = st + STG_BL + (off ^ ((off >> 3) & 0x70));
            src = B + (size_t)row * KS + 1024 + kb + c * 8;
        }
        cp16s(dst, src);
    }
}

// Issue the 12 MMAs of one chunk (4 x K16, 3 split terms). Caller = elect.
DI void issue_chunk(uint32_t tmem, uint32_t st, bool first) {
    uint64_t dAh = MK_DESC(st + STG_AH);
    uint64_t dAl = MK_DESC(st + STG_AL);
    uint64_t dBh = MK_DESC(st + STG_BH);
    uint64_t dBl = MK_DESC(st + STG_BL);
#pragma unroll
    for (int k = 0; k < 4; k++) {
        mma_f16_ss(tmem, dAh + 2 * k, dBh + 2 * k, (first && k == 0) ? 0u : 1u);
        mma_f16_ss(tmem, dAh + 2 * k, dBl + 2 * k, 1u);
        mma_f16_ss(tmem, dAl + 2 * k, dBh + 2 * k, 1u);
    }
}

// One GEMM phase: nch chunks (chunks 0..15 from A0/B0, 16..31 from A1/B1),
// result -> dd[64] (fp32 bits) per thread (row=tid), running chunk counter.
// 4 stages, 4 mbarriers (one per stage): chunk g -> stage g&3, mbar g&3,
// arrival k=g>>2 completes parity (g>>2)&1. Stage-reuse wait is on chunk g-2
// (loads for g+2 overwrite stage (g+2)&3 = (g-2)&3).
DI void do_phase(int nch,
                 const __nv_bfloat16* A0, const __nv_bfloat16* B0,
                 const __nv_bfloat16* A1, const __nv_bfloat16* B1,
                 uint32_t sbase, uint32_t tmem, uint32_t mbb,
                 int& ctr, uint32_t* dd, int tid, int wid) {
#pragma unroll
    for (int i = 0; i < 2; i++) {
        int g = ctr + i;
        load_chunk(sbase + (g & 3) * STG_SZ, A0, B0, i, tid);
        cp_commit();
    }
    for (int i = 0; i < nch; i++) {
        int g = ctr + i;
        cp_wait1();
        __syncthreads();
        if (wid == 0) {
            if (elect1()) {
                asm volatile("fence.proxy.async.shared::cta;" ::: "memory");
                issue_chunk(tmem, sbase + (g & 3) * STG_SZ, i == 0);
                T5_COMMIT(mbb + (g & 3) * 8);
            }
        }
        if (g >= 2) {
            int gw = g - 2;
            MBAR_WAIT(mbb + (gw & 3) * 8, (uint32_t)((gw >> 2) & 1));
        }
        if (i + 2 < nch) {
            int j = i + 2, gg = g + 2;
            load_chunk(sbase + (gg & 3) * STG_SZ,
                       (j >= 16) ? A1 : A0, (j >= 16) ? B1 : B0, j & 15, tid);
        }
        cp_commit();
    }
    int gl = ctr + nch - 1;
    MBAR_WAIT(mbb + (gl & 3) * 8, (uint32_t)((gl >> 2) & 1));
    T5_FENCE_AFTER();
    T5_LD_X32(dd, tmem);
    T5_LD_X32(dd + 32, tmem + 32);
    T5_WAIT_LD();
    T5_FENCE_BEFORE();
    ctr += nch;
}
#endif  // T5_OK

// ----------------------- persistent scan (1 kernel) -------------------------
// 64 CTAs x 128 threads. CTA bid: N-tile n0=bid*64 ([i|f|g|o]x16 h-cols,
// h-cols j0=bid*16), M=128 = full batch.
__global__ void __launch_bounds__(128) k_scan(float* __restrict__ out) {
    extern __shared__ char dyn[];
    const int tid = threadIdx.x, wid = tid >> 5;
    const int n0 = blockIdx.x * 64, j0 = blockIdx.x * 16;

    float c0[16], c1[16];
#pragma unroll
    for (int i = 0; i < 16; i++) { c0[i] = 0.0f; c1[i] = 0.0f; }

#if T5_OK
    // ======================= tcgen05 implementation ========================
    __shared__ uint64_t s_mbar[4];
    __shared__ uint32_t s_tptr;

    uint32_t sbase = (smem_u32(dyn) + 1023u) & ~1023u;
    uint32_t mbb = smem_u32(&s_mbar[0]);

    if (wid == 0) T5_ALLOC(smem_u32(&s_tptr), 512);
    if (tid == 0) {
#pragma unroll
        for (int m = 0; m < 4; m++) MBAR_INIT(mbb + m * 8, 1);
    }
    __syncthreads();
    uint32_t tmem;
    asm volatile("ld.shared.b32 %0, [%1];" : "=r"(tmem) : "r"(smem_u32(&s_tptr)));

    int ctr = 0;
    uint32_t dd[64];

    for (int t = 0; t < SEQ; t++) {
        const int p = t & 1;

        // ---- Phase A: gates0 = h0[p] @ Whh0'^T  (+gates_x in epilogue) ----
        do_phase(16, g_h0s[p], g_Whh0s + (size_t)n0 * KS,
                 g_h0s[p], g_Whh0s + (size_t)n0 * KS,
                 sbase, tmem, mbb, ctr, dd, tid, wid);
        {
            const float* gx = g_gates_x + ((size_t)(t * BATCH + tid)) * G4 + n0;
            __nv_bfloat16* hb = g_h0s[p ^ 1] + (size_t)tid * KS + j0;
#pragma unroll
            for (int jj = 0; jj < 16; jj++) {
                float iv = sigf (__uint_as_float(dd[jj])      + gx[jj]);
                float fv = sigf (__uint_as_float(dd[16 + jj]) + gx[16 + jj]);
                float gv = tanhf(__uint_as_float(dd[32 + jj]) + gx[32 + jj]);
                float ov = sigf (__uint_as_float(dd[48 + jj]) + gx[48 + jj]);
                float cn = fv * c0[jj] + iv * gv;
                c0[jj] = cn;
                float h = ov * tanhf(cn);
                __nv_bfloat16 hi = __float2bfloat16(h);
                hb[jj]        = hi;
                hb[1024 + jj] = __float2bfloat16(h - __bfloat162float(hi));
            }
        }
        grid_bar();

        // ---- Phase B: gates1 = h0[p^1]@Wih1'^T + h1[p]@Whh1'^T + bias1 ----
        do_phase(32, g_h0s[p ^ 1], g_Wih1s + (size_t)n0 * KS,
                 g_h1s[p], g_Whh1s + (size_t)n0 * KS,
                 sbase, tmem, mbb, ctr, dd, tid, wid);
        {
            const float* bs = g_bias1 + n0;
            __nv_bfloat16* hb = g_h1s[p ^ 1] + (size_t)tid * KS + j0;
            float* op = out + ((size_t)tid * SEQ + t) * HDIM + j0;
#pragma unroll
            for (int jj = 0; jj < 16; jj++) {
                float iv = sigf (__uint_as_float(dd[jj])      + bs[jj]);
                float fv = sigf (__uint_as_float(dd[16 + jj]) + bs[16 + jj]);
                float gv = tanhf(__uint_as_float(dd[32 + jj]) + bs[32 + jj]);
                float ov = sigf (__uint_as_float(dd[48 + jj]) + bs[48 + jj]);
                float cn = fv * c1[jj] + iv * gv;
                c1[jj] = cn;
                float h = ov * tanhf(cn);
                __nv_bfloat16 hi = __float2bfloat16(h);
                hb[jj]        = hi;
                hb[1024 + jj] = __float2bfloat16(h - __bfloat162float(hi));
                op[jj] = h;
            }
        }
        // no grid barrier here (parity double-buffering; see R9-R11 analysis)
    }

    __syncthreads();
    if (wid == 0) { T5_RELINQ(); T5_DEALLOC(tmem, 512); }

#else
    // =============== mma.sync fallback (non-'a' target pass) ===============
    __nv_bfloat16* sA = (__nv_bfloat16*)dyn;
    __nv_bfloat16* sB = sA + 4 * 128 * SSTR;
    float* sAcc = (float*)dyn;
    const int lane = tid & 31, warp = tid >> 5;
    const int wm = warp & 1, wn = warp >> 1;

    float acc[64];

    auto epi_to_smem = [&]() {
        __syncthreads();
#pragma unroll
        for (int mi = 0; mi < 4; mi++)
#pragma unroll
            for (int ng = 0; ng < 2; ng++)
#pragma unroll
                for (int hf = 0; hf < 2; hf++) {
                    const float* a4 = acc + ((mi * 4) + 2 * ng + hf) * 4;
                    int r = wm * 64 + mi * 16 + (lane >> 2);
                    int c = wn * 32 + ng * 16 + hf * 8 + ((lane & 3) << 1);
                    sAcc[r * 68 + c]           = a4[0];
                    sAcc[r * 68 + c + 1]       = a4[1];
                    sAcc[(r + 8) * 68 + c]     = a4[2];
                    sAcc[(r + 8) * 68 + c + 1] = a4[3];
                }
        __syncthreads();
    };

    for (int t = 0; t < SEQ; t++) {
        const int p = t & 1;

#pragma unroll
        for (int i = 0; i < 64; i++) acc[i] = 0.0f;
        gemm_cp<128, 64, 2, 2, 128>(g_h0s[p], g_Whh0s + (size_t)n0 * KS, acc, sA, sB);
        epi_to_smem();
        {
            const float* gx = g_gates_x + ((size_t)(t * BATCH + tid)) * G4 + n0;
            const float* ga = sAcc + tid * 68;
            __nv_bfloat16* hb = g_h0s[p ^ 1] + (size_t)tid * KS + j0;
#pragma unroll
            for (int jj = 0; jj < 16; jj++) {
                float iv = sigf (ga[jj]      + gx[jj]);
                float fv = sigf (ga[16 + jj] + gx[16 + jj]);
                float gv = tanhf(ga[32 + jj] + gx[32 + jj]);
                float ov = sigf (ga[48 + jj] + gx[48 + jj]);
                float cn = fv * c0[jj] + iv * gv;
                c0[jj] = cn;
                float h = ov * tanhf(cn);
                __nv_bfloat16 hi = __float2bfloat16(h);
                hb[jj]        = hi;
                hb[1024 + jj] = __float2bfloat16(h - __bfloat162float(hi));
            }
        }
        grid_bar();

#pragma unroll
        for (int i = 0; i < 64; i++) acc[i] = 0.0f;
        gemm_cp<128, 64, 2, 2, 128>(g_h0s[p ^ 1], g_Wih1s + (size_t)n0 * KS, acc, sA, sB);
        gemm_cp<128, 64, 2, 2, 128>(g_h1s[p], g_Whh1s + (size_t)n0 * KS, acc, sA, sB);
        epi_to_smem();
        {
            const float* bs = g_bias1 + n0;
            const float* ga = sAcc + tid * 68;
            __nv_bfloat16* hb = g_h1s[p ^ 1] + (size_t)tid * KS + j0;
            float* op = out + ((size_t)tid * SEQ + t) * HDIM + j0;
#pragma unroll
            for (int jj = 0; jj < 16; jj++) {
                float iv = sigf (ga[jj]      + bs[jj]);
                float fv = sigf (ga[16 + jj] + bs[16 + jj]);
                float gv = tanhf(ga[32 + jj] + bs[32 + jj]);
                float ov = sigf (ga[48 + jj] + bs[48 + jj]);
                float cn = fv * c1[jj] + iv * gv;
                c1[jj] = cn;
                float h = ov * tanhf(cn);
                __nv_bfloat16 hi = __float2bfloat16(h);
                hb[jj]        = hi;
                hb[1024 + jj] = __float2bfloat16(h - __bfloat162float(hi));
                op[jj] = h;
            }
        }
        __syncthreads();
    }
#endif
}

// -------------------------------- launcher ----------------------------------
extern "C" void kernel_launch(void* const* d_in, const int* in_sizes, int n_in,
                              void* d_out, int out_size) {
    const float* x     = (const float*)d_in[0];
    const float* W_ih0 = (const float*)d_in[1];
    const float* b_ih0 = (const float*)d_in[2];
    const float* W_hh0 = (const float*)d_in[3];
    const float* b_hh0 = (const float*)d_in[4];
    const float* W_ih1 = (const float*)d_in[5];
    const float* b_ih1 = (const float*)d_in[6];
    const float* W_hh1 = (const float*)d_in[7];
    const float* b_hh1 = (const float*)d_in[8];
    float* out = (float*)d_out;

    cudaFuncSetAttribute(k_gemm_pre, cudaFuncAttributeMaxDynamicSharedMemorySize, PRE_SMEM);
    cudaFuncSetAttribute(k_scan,     cudaFuncAttributeMaxDynamicSharedMemorySize, SCAN_DYN);

    // prep (2 launches -- exactly 4 total so the fixed ncu window hits k_scan)
    k_prep_w<<<(4 * G4 * FDIM + 255) / 256, 256>>>(W_ih0, W_hh0, W_ih1, W_hh1,
                                                   b_ih0, b_hh0, b_ih1, b_hh1);
    k_prep_x<<<(MTOT * FDIM + 255) / 256, 256>>>(x);

    // input-projection GEMM for all timesteps
    k_gemm_pre<<<dim3(G4 / 128, MTOT / 128), 256, PRE_SMEM>>>();

    // persistent scan (tcgen05 on arch-specific cubin, mma.sync otherwise)
    k_scan<<<NCTA, 128, SCAN_DYN>>>(out);
}

// round 17
// speedup vs baseline: 1.0511x; 1.0511x over previous
#include <cuda_runtime.h>
#include <cuda_bf16.h>
#include <cstdint>
#include <math.h>

// ---------------------------------------------------------------------------
// CustomLSTM: 2-layer LSTM, B=128, T=256, F=H=1024.
// Round 15:
//   * Scan pipeline rebuilt as single-thread TMA-bulk + mbarrier machine:
//     operands pre-blocked & pre-swizzled in gmem; 4 cp.async.bulk per chunk
//     (tx-counted full barrier) replace 3072 LDGSTS; tcgen05.commit -> empty
//     barrier gates stage reuse; per-phase done barrier releases the CTA.
//     No per-chunk __syncthreads / all-thread waits at all.
//   * MMA protocol (idesc/SW128 desc/TMEM/LDTM cell fusion) unchanged.
//   * Fallback (plain sm_103 pass) unchanged, uses flat layouts.
// ---------------------------------------------------------------------------

#define DI __device__ __forceinline__

// tcgen05 available only in arch-specific device passes (sm_103a etc.)
#if defined(__CUDA_ARCH__) && !(defined(__CUDA_ARCH_FEAT_SM103_ALL) ||       \
    defined(__CUDA_ARCH_FEAT_SM100_ALL) || defined(__CUDA_ARCH_SPECIFIC__) ||\
    defined(__CUDA_ARCH_FAMILY_SPECIFIC__))
#define T5_OK 0
#else
#define T5_OK 1
#endif

constexpr int BATCH = 128;
constexpr int SEQ   = 256;
constexpr int FDIM  = 1024;
constexpr int HDIM  = 1024;
constexpr int G4    = 4096;          // 4*H
constexpr int KS    = 2048;          // compact split width [hi|lo]
constexpr int MTOT  = BATCH * SEQ;   // 32768
constexpr int NCTA  = 64;            // persistent scan CTAs
constexpr int SSTR  = 72;            // smem row stride for mma.sync paths

// scan smem stage layout (bytes) for tcgen05 path
constexpr int STG_AH = 0;            // 128 rows x 128B  (16KB)
constexpr int STG_AL = 16384;        // 16KB
constexpr int STG_BH = 32768;        // 64 rows x 128B   (8KB)
constexpr int STG_BL = 40960;        // 8KB
constexpr int STG_SZ = 49152;        // 48KB per stage
constexpr int NSTG   = 4;
constexpr int PFD    = 3;            // prefetch depth
constexpr int SCAN_DYN = NSTG * STG_SZ + 1024;   // 197632 (covers fallback too)

// idesc kind::f16: F32 acc, bf16 a/b, N=64, M=128
constexpr uint32_t IDESC_F16 =
    (1u << 4) | (1u << 7) | (1u << 10) | ((64u / 8) << 17) | ((128u / 16) << 24);

// SW128 smem descriptor base (Blackwell): layout=SW128, ver=1, SBO=64, LBO=1
constexpr uint64_t DESC_SW128 =
    (uint64_t(2) << 61) | (uint64_t(1) << 46) | (uint64_t(64) << 32) | (uint64_t(1) << 16);
#define MK_DESC(addr) (DESC_SW128 | ((uint64_t)((addr) >> 4) & 0x3FFF))

// ------------------------- device scratch (globals) ------------------------
// flat layouts (pre-GEMM + fallback scan)
__device__ __nv_bfloat16 g_Wih0s[(size_t)G4 * KS];
__device__ __nv_bfloat16 g_Whh0s[(size_t)G4 * KS];
__device__ __nv_bfloat16 g_Wih1s[(size_t)G4 * KS];
__device__ __nv_bfloat16 g_Whh1s[(size_t)G4 * KS];
__device__ __nv_bfloat16 g_xs[(size_t)MTOT * KS];             // split x [hi|lo]
__device__ float         g_gates_x[(size_t)SEQ * BATCH * G4]; // [t][b][c] permuted
__device__ __nv_bfloat16 g_h0s[2][(size_t)BATCH * KS];        // fallback h
__device__ __nv_bfloat16 g_h1s[2][(size_t)BATCH * KS];
__device__ float         g_bias0[G4];   // permuted
__device__ float         g_bias1[G4];   // permuted

// blocked pre-swizzled layouts (tcgen05 scan): weight tile = 64 rows; per tile
// 32 blocks (16 hi + 16 lo) of 64 rows x 128B = 8KB. h: 32 blocks of 128x128B.
__device__ __align__(1024) __nv_bfloat16 g_Whh0b[(size_t)64 * 32 * 4096];
__device__ __align__(1024) __nv_bfloat16 g_Wih1b[(size_t)64 * 32 * 4096];
__device__ __align__(1024) __nv_bfloat16 g_Whh1b[(size_t)64 * 32 * 4096];
__device__ __align__(1024) __nv_bfloat16 g_h0b[2][(size_t)32 * 8192];
__device__ __align__(1024) __nv_bfloat16 g_h1b[2][(size_t)32 * 8192];

__device__ unsigned g_bar_cnt;
__device__ unsigned g_bar_gen;

// ------------------------------ small helpers ------------------------------
DI float sigf(float x) { return 1.0f / (1.0f + __expf(-x)); }

DI int gate_perm(int n) {            // row n -> permuted col
    int g = n >> 10, j = n & 1023;
    return ((j >> 4) << 6) + (g << 4) + (j & 15);
}

DI uint32_t smem_u32(const void* p) {
    uint32_t a;
    asm("{ .reg .u64 t; cvta.to.shared.u64 t, %1; cvt.u32.u64 %0, t; }"
        : "=r"(a) : "l"(p));
    return a;
}

DI void ldsm4(uint32_t* r, const __nv_bfloat16* p) {
    uint32_t a = (uint32_t)__cvta_generic_to_shared(p);
    asm volatile("ldmatrix.sync.aligned.m8n8.x4.shared.b16 {%0,%1,%2,%3}, [%4];"
                 : "=r"(r[0]), "=r"(r[1]), "=r"(r[2]), "=r"(r[3]) : "r"(a));
}

DI void mma16816(float* d, const uint32_t* a, uint32_t b0, uint32_t b1) {
    asm volatile(
        "mma.sync.aligned.m16n8k16.row.col.f32.bf16.bf16.f32 "
        "{%0,%1,%2,%3}, {%4,%5,%6,%7}, {%8,%9}, {%0,%1,%2,%3};"
        : "+f"(d[0]), "+f"(d[1]), "+f"(d[2]), "+f"(d[3])
        : "r"(a[0]), "r"(a[1]), "r"(a[2]), "r"(a[3]), "r"(b0), "r"(b1));
}

DI void cp16(void* dst, const void* src) {
    uint32_t d = (uint32_t)__cvta_generic_to_shared(dst);
    asm volatile("cp.async.cg.shared.global [%0], [%1], 16;\n" :: "r"(d), "l"(src));
}
DI void cp_commit() { asm volatile("cp.async.commit_group;\n" ::: "memory"); }
DI void cp_wait2()  { asm volatile("cp.async.wait_group 2;\n"  ::: "memory"); }

DI void grid_bar() {
    __syncthreads();
    if (threadIdx.x == 0) {
        unsigned gen = *(volatile unsigned*)&g_bar_gen;
        __threadfence();
        if (atomicAdd(&g_bar_cnt, 1u) == NCTA - 1u) {
            atomicExch(&g_bar_cnt, 0u);
            __threadfence();
            atomicExch(&g_bar_gen, gen + 1u);
        } else {
            while (*(volatile unsigned*)&g_bar_gen == gen) { __nanosleep(32); }
        }
        __threadfence();
    }
    __syncthreads();
}

// ---------------------------- tcgen05 wrappers ------------------------------
#if T5_OK
#define T5_ALLOC(smem_addr, n) \
    asm volatile("tcgen05.alloc.cta_group::1.sync.aligned.shared::cta.b32 [%0], %1;" \
                 :: "r"(smem_addr), "r"((uint32_t)(n)) : "memory")
#define T5_DEALLOC(tmem, n) \
    asm volatile("tcgen05.dealloc.cta_group::1.sync.aligned.b32 %0, %1;" \
                 :: "r"(tmem), "r"((uint32_t)(n)))
#define T5_RELINQ() \
    asm volatile("tcgen05.relinquish_alloc_permit.cta_group::1.sync.aligned;")
#define T5_COMMIT(mb) \
    asm volatile("tcgen05.commit.cta_group::1.mbarrier::arrive::one.shared::cluster.b64 [%0];" \
                 :: "r"(mb) : "memory")
#define T5_FENCE_AFTER()  asm volatile("tcgen05.fence::after_thread_sync;" ::: "memory")
#define T5_FENCE_BEFORE() asm volatile("tcgen05.fence::before_thread_sync;" ::: "memory")
#define T5_WAIT_LD()      asm volatile("tcgen05.wait::ld.sync.aligned;" ::: "memory")

#define MBAR_INIT(mb, cnt) \
    asm volatile("mbarrier.init.shared.b64 [%0], %1;" :: "r"(mb), "r"((uint32_t)(cnt)) : "memory")

#define MBAR_WAIT(mb, par) do {                                              \
    uint32_t _mb = (mb), _pp = (par), _done;                                 \
    asm volatile("{\n\t.reg .pred p;\n\t"                                    \
        "mbarrier.try_wait.parity.acquire.cta.shared::cta.b64 p, [%1], %2;\n\t" \
        "selp.b32 %0, 1, 0, p;\n\t}" : "=r"(_done) : "r"(_mb), "r"(_pp) : "memory"); \
    if (!_done) {                                                            \
        asm volatile("{\n\t.reg .pred P1;\n\t"                               \
            "WL_%=:\n\t"                                                     \
            "mbarrier.try_wait.parity.acquire.cta.shared::cta.b64 P1, [%0], %1, 0x989680;\n\t" \
            "@P1 bra.uni WD_%=;\n\t"                                         \
            "bra.uni WL_%=;\n\t"                                             \
            "WD_%=:\n\t}" :: "r"(_mb), "r"(_pp) : "memory");                 \
    }                                                                        \
} while (0)

#define T5_LD_X32(r, tm)                                                     \
    asm volatile("tcgen05.ld.sync.aligned.32x32b.x32.b32 "                   \
        "{%0, %1, %2, %3, %4, %5, %6, %7, "                                  \
        " %8, %9, %10, %11, %12, %13, %14, %15, "                            \
        " %16, %17, %18, %19, %20, %21, %22, %23, "                          \
        " %24, %25, %26, %27, %28, %29, %30, %31}, [%32];"                   \
        : "=r"((r)[0]),  "=r"((r)[1]),  "=r"((r)[2]),  "=r"((r)[3]),         \
          "=r"((r)[4]),  "=r"((r)[5]),  "=r"((r)[6]),  "=r"((r)[7]),         \
          "=r"((r)[8]),  "=r"((r)[9]),  "=r"((r)[10]), "=r"((r)[11]),        \
          "=r"((r)[12]), "=r"((r)[13]), "=r"((r)[14]), "=r"((r)[15]),        \
          "=r"((r)[16]), "=r"((r)[17]), "=r"((r)[18]), "=r"((r)[19]),        \
          "=r"((r)[20]), "=r"((r)[21]), "=r"((r)[22]), "=r"((r)[23]),        \
          "=r"((r)[24]), "=r"((r)[25]), "=r"((r)[26]), "=r"((r)[27]),        \
          "=r"((r)[28]), "=r"((r)[29]), "=r"((r)[30]), "=r"((r)[31])         \
        : "r"(tm))

DI void mma_f16_ss(uint32_t d, uint64_t a, uint64_t b, uint32_t en) {
    asm volatile(
        "{\n\t.reg .pred p;\n\tsetp.ne.u32 p, %4, 0;\n\t"
        "tcgen05.mma.cta_group::1.kind::f16 [%0], %1, %2, %3, {%5,%5,%5,%5}, p;\n\t}"
        :: "r"(d), "l"(a), "l"(b), "r"(IDESC_F16), "r"(en), "r"(0u) : "memory");
}

DI void tbulk(uint32_t dst, const void* src, uint32_t bytes, uint32_t mb) {
    asm volatile(
        "cp.async.bulk.shared::cluster.global.mbarrier::complete_tx::bytes "
        "[%0], [%1], %2, [%3];"
        :: "r"(dst), "l"(src), "r"(bytes), "r"(mb) : "memory");
}

// Issue one chunk's TMA: expect_tx(48KB) + 4 bulk copies. Single thread.
DI void tma_chunk(uint32_t stg, const __nv_bfloat16* Ab, const __nv_bfloat16* Bb,
                  int kc, uint32_t fmb) {
    asm volatile("mbarrier.arrive.expect_tx.shared.b64 _, [%0], %1;"
                 :: "r"(fmb), "r"((uint32_t)STG_SZ) : "memory");
    tbulk(stg + STG_AH, Ab + (size_t)kc * 8192, 16384, fmb);        // Ah
    tbulk(stg + STG_AL, Ab + (size_t)(16 + kc) * 8192, 16384, fmb); // Al
    tbulk(stg + STG_BH, Bb + (size_t)kc * 4096, 8192, fmb);         // Bh
    tbulk(stg + STG_BL, Bb + (size_t)(16 + kc) * 4096, 8192, fmb);  // Bl
}

// Issue the 12 MMAs of one chunk (4 x K16, 3 split terms). Single thread.
DI void issue_chunk(uint32_t tmem, uint32_t st, bool first) {
    uint64_t dAh = MK_DESC(st + STG_AH);
    uint64_t dAl = MK_DESC(st + STG_AL);
    uint64_t dBh = MK_DESC(st + STG_BH);
    uint64_t dBl = MK_DESC(st + STG_BL);
#pragma unroll
    for (int k = 0; k < 4; k++) {
        mma_f16_ss(tmem, dAh + 2 * k, dBh + 2 * k, (first && k == 0) ? 0u : 1u);
        mma_f16_ss(tmem, dAh + 2 * k, dBl + 2 * k, 1u);
        mma_f16_ss(tmem, dAl + 2 * k, dBh + 2 * k, 1u);
    }
}

// One GEMM phase: nch chunks (i<16 -> A0/B0, i>=16 -> A1/B1, kc=i&15).
// Thread 0 runs the whole TMA+MMA machine; everyone else waits on `dn`.
// Stage s=g&3; full-wait parity (g>>2)&1; empty-wait (stage reuse) parity
// ((g>>2)+1)&1 (use #0 passes on the fresh barrier).
DI void do_phase_t5(int nch,
                    const __nv_bfloat16* A0, const __nv_bfloat16* B0,
                    const __nv_bfloat16* A1, const __nv_bfloat16* B1,
                    uint32_t sbase, uint32_t tmem,
                    uint32_t fullb, uint32_t emptyb, uint32_t dn,
                    int& gctr, int& ph, uint32_t* dd, int tid) {
    if (tid == 0) {
        T5_FENCE_AFTER();
#pragma unroll 1
        for (int j = 0; j < PFD; j++) {              // prologue (nch >= 16 > PFD)
            int gc = gctr + j;
            MBAR_WAIT(emptyb + (gc & 3) * 8, (uint32_t)(((gc >> 2) + 1) & 1));
            tma_chunk(sbase + (gc & 3) * STG_SZ,
                      (j < 16) ? A0 : A1, (j < 16) ? B0 : B1, j & 15,
                      fullb + (gc & 3) * 8);
        }
#pragma unroll 1
        for (int i = 0; i < nch; i++) {
            int gc = gctr + i;
            MBAR_WAIT(fullb + (gc & 3) * 8, (uint32_t)((gc >> 2) & 1));
            issue_chunk(tmem, sbase + (gc & 3) * STG_SZ, i == 0);
            T5_COMMIT(emptyb + (gc & 3) * 8);
            if (i + PFD < nch) {
                int j = i + PFD, gc2 = gc + PFD;
                MBAR_WAIT(emptyb + (gc2 & 3) * 8, (uint32_t)(((gc2 >> 2) + 1) & 1));
                tma_chunk(sbase + (gc2 & 3) * STG_SZ,
                          (j < 16) ? A0 : A1, (j < 16) ? B0 : B1, j & 15,
                          fullb + (gc2 & 3) * 8);
            }
        }
        T5_COMMIT(dn);
    }
    MBAR_WAIT(dn, (uint32_t)(ph & 1));
    T5_FENCE_AFTER();
    T5_LD_X32(dd, tmem);
    T5_LD_X32(dd + 32, tmem + 32);
    T5_WAIT_LD();
    T5_FENCE_BEFORE();
    gctr += nch;
    ph++;
}
#endif  // T5_OK

// ----------------------- fused prep kernels (2 launches) --------------------
__global__ void k_prep_w(const float* __restrict__ W0, const float* __restrict__ W1,
                         const float* __restrict__ W2, const float* __restrict__ W3,
                         const float* __restrict__ b_ih0, const float* __restrict__ b_hh0,
                         const float* __restrict__ b_ih1, const float* __restrict__ b_hh1) {
    size_t idx = (size_t)blockIdx.x * blockDim.x + threadIdx.x;
    if (idx < (size_t)G4) {                        // fused bias prep
        int i = (int)idx;
        int c = gate_perm(i);
        g_bias0[c] = b_ih0[i] + b_hh0[i];
        g_bias1[c] = b_ih1[i] + b_hh1[i];
    }
    if (idx >= (size_t)4 * G4 * FDIM) return;
    int which = (int)(idx >> 22);
    int r = (int)(idx & 4194303);
    const float* W = which == 0 ? W0 : which == 1 ? W1 : which == 2 ? W2 : W3;
    __nv_bfloat16* Ws = which == 0 ? g_Wih0s : which == 1 ? g_Whh0s
                       : which == 2 ? g_Wih1s : g_Whh1s;
    int n = r >> 10, k = r & 1023;
    int c = gate_perm(n);
    float v = W[r];
    __nv_bfloat16 hi = __float2bfloat16(v);
    __nv_bfloat16 lo = __float2bfloat16(v - __bfloat162float(hi));
    __nv_bfloat16* row = Ws + (size_t)c * KS;      // flat (pre-GEMM / fallback)
    row[k] = hi; row[1024 + k] = lo;
    if (which >= 1) {                              // blocked pre-swizzled (scan)
        __nv_bfloat16* Wb = which == 1 ? g_Whh0b : which == 2 ? g_Wih1b : g_Whh1b;
        uint8_t* bb = (uint8_t*)Wb;
        int tile = c >> 6, rw = c & 63;
        uint32_t off = (uint32_t)rw * 128u + (uint32_t)((k & 63) << 1);
        uint32_t soff = off ^ ((off >> 3) & 0x70);
        size_t tb = (size_t)tile * 262144u;        // 32 blocks * 8KB
        *(__nv_bfloat16*)(bb + tb + (size_t)(k >> 6) * 8192u + soff) = hi;
        *(__nv_bfloat16*)(bb + tb + (size_t)(16 + (k >> 6)) * 8192u + soff) = lo;
    }
}

__global__ void k_prep_x(const float* __restrict__ x) {
    size_t idx = (size_t)blockIdx.x * blockDim.x + threadIdx.x;
    if (idx < (size_t)BATCH * KS) {                // fused h-state init (fallback)
        __nv_bfloat16 z = __float2bfloat16(0.0f);
        g_h0s[0][idx] = z; g_h1s[0][idx] = z;
    }
    if (idx < (size_t)32 * 8192) {                 // blocked h init (t5 scan)
        __nv_bfloat16 z = __float2bfloat16(0.0f);
        g_h0b[0][idx] = z; g_h1b[0][idx] = z;
    }
    if (idx >= (size_t)MTOT * FDIM) return;
    int m = (int)(idx >> 10), k = (int)(idx & 1023);
    float v = x[idx];
    __nv_bfloat16 hi = __float2bfloat16(v);
    __nv_bfloat16 lo = __float2bfloat16(v - __bfloat162float(hi));
    __nv_bfloat16* row = g_xs + (size_t)m * KS;
    row[k] = hi; row[1024 + k] = lo;
}

// ------------- mma.sync cp.async 4-stage pipeline (pre-GEMM + fallback) -----
template <int BM, int BN, int WR, int WC, int NTH>
DI void gemm_cp(const __nv_bfloat16* __restrict__ A0,
                const __nv_bfloat16* __restrict__ B0,
                float* acc, __nv_bfloat16* sA, __nv_bfloat16* sB) {
    constexpr int WTM = BM / WR, WTN = BN / WC;
    constexpr int MT = WTM / 16, NG = WTN / 16;
    constexpr int AV = BM * 8 / NTH, BV = BN * 8 / NTH;
    constexpr int NITER = 32;
    constexpr int SZA = BM * SSTR, SZB = BN * SSTR;
    const int tid = threadIdx.x;
    const int warp = tid >> 5, lane = tid & 31;
    const int wm = warp % WR, wn = warp / WR;
    const int lr = lane & 15, lc = (lane >> 4) << 3;

    auto fetch = [&](int c, int st) {
        int k32 = c << 5;
#pragma unroll
        for (int i = 0; i < AV; i++) {
            int v = tid + i * NTH;
            int row = v >> 3, rem = v & 7, hf = rem >> 2, cp = (rem & 3) << 3;
            cp16(sA + st * SZA + row * SSTR + (hf << 5) + cp,
                 A0 + (size_t)row * KS + hf * 1024 + k32 + cp);
        }
#pragma unroll
        for (int i = 0; i < BV; i++) {
            int v = tid + i * NTH;
            int row = v >> 3, rem = v & 7, hf = rem >> 2, cp = (rem & 3) << 3;
            cp16(sB + st * SZB + row * SSTR + (hf << 5) + cp,
                 B0 + (size_t)row * KS + hf * 1024 + k32 + cp);
        }
        cp_commit();
    };

#pragma unroll
    for (int s = 0; s < 3; s++) fetch(s, s);

    for (int it = 0; it < NITER; it++) {
        cp_wait2();
        __syncthreads();
        if (it + 3 < NITER) fetch(it + 3, (it + 3) & 3);
        else cp_commit();
        const __nv_bfloat16* cA = sA + (it & 3) * SZA;
        const __nv_bfloat16* cB = sB + (it & 3) * SZB;
#pragma unroll
        for (int kk = 0; kk < 32; kk += 16) {
            uint32_t rah[MT][4], ral[MT][4], rbh[NG][4], rbl[NG][4];
#pragma unroll
            for (int mi = 0; mi < MT; mi++) {
                const __nv_bfloat16* p = cA + (wm * WTM + mi * 16 + lr) * SSTR + kk + lc;
                ldsm4(rah[mi], p);
                ldsm4(ral[mi], p + 32);
            }
#pragma unroll
            for (int ng = 0; ng < NG; ng++) {
                const __nv_bfloat16* p = cB + (wn * WTN + ng * 16 + lr) * SSTR + kk + lc;
                ldsm4(rbh[ng], p);
                ldsm4(rbl[ng], p + 32);
            }
#pragma unroll
            for (int mi = 0; mi < MT; mi++)
#pragma unroll
                for (int ng = 0; ng < NG; ng++) {
                    float* a0 = acc + ((mi * 2 * NG) + 2 * ng) * 4;
                    float* a1 = a0 + 4;
                    mma16816(a0, rah[mi], rbh[ng][0], rbh[ng][2]);
                    mma16816(a1, rah[mi], rbh[ng][1], rbh[ng][3]);
                    mma16816(a0, rah[mi], rbl[ng][0], rbl[ng][2]);
                    mma16816(a1, rah[mi], rbl[ng][1], rbl[ng][3]);
                    mma16816(a0, ral[mi], rbh[ng][0], rbh[ng][2]);
                    mma16816(a1, ral[mi], rbh[ng][1], rbh[ng][3]);
                }
        }
    }
}

constexpr int PRE_SMEM = 4 * (128 + 128) * SSTR * (int)sizeof(__nv_bfloat16);

__global__ void __launch_bounds__(256) k_gemm_pre() {
    extern __shared__ __nv_bfloat16 smem[];
    __nv_bfloat16* sA = smem;
    __nv_bfloat16* sB = smem + 4 * 128 * SSTR;
    const int m0 = blockIdx.y * 128, n0 = blockIdx.x * 128;
    float acc[64];
#pragma unroll
    for (int i = 0; i < 64; i++) acc[i] = 0.0f;

    gemm_cp<128, 128, 2, 4, 256>(g_xs + (size_t)m0 * KS,
                                 g_Wih0s + (size_t)n0 * KS, acc, sA, sB);

    const int lane = threadIdx.x & 31, warp = threadIdx.x >> 5;
    const int wm = warp & 1, wn = warp >> 1;
#pragma unroll
    for (int mi = 0; mi < 4; mi++)
#pragma unroll
        for (int ng = 0; ng < 2; ng++)
#pragma unroll
            for (int hf = 0; hf < 2; hf++) {
                const float* a4 = acc + ((mi * 4) + 2 * ng + hf) * 4;
                int r = m0 + wm * 64 + mi * 16 + (lane >> 2);
                int c = n0 + wn * 32 + ng * 16 + hf * 8 + ((lane & 3) << 1);
                {
                    int b = r >> 8, t = r & 255;
                    size_t d = (size_t)(t * BATCH + b) * G4 + c;
                    g_gates_x[d]     = a4[0] + g_bias0[c];
                    g_gates_x[d + 1] = a4[1] + g_bias0[c + 1];
                }
                {
                    int r2 = r + 8;
                    int b = r2 >> 8, t = r2 & 255;
                    size_t d = (size_t)(t * BATCH + b) * G4 + c;
                    g_gates_x[d]     = a4[2] + g_bias0[c];
                    g_gates_x[d + 1] = a4[3] + g_bias0[c + 1];
                }
            }
}

// ----------------------- persistent scan (1 kernel) -------------------------
// 64 CTAs x 128 threads. CTA bid: gate tile n0=bid*64 ([i|f|g|o]x16 h-cols,
// h-cols j0=bid*16), M=128 = full batch. Thread tid = batch row.
__global__ void __launch_bounds__(128) k_scan(float* __restrict__ out) {
    extern __shared__ char dyn[];
    const int tid = threadIdx.x, wid = tid >> 5;
    const int bid = blockIdx.x;
    const int n0 = bid * 64, j0 = bid * 16;

    float c0[16], c1[16];
#pragma unroll
    for (int i = 0; i < 16; i++) { c0[i] = 0.0f; c1[i] = 0.0f; }

#if T5_OK
    // ======================= tcgen05 TMA implementation ====================
    __shared__ __align__(8) uint64_t s_full[4];
    __shared__ __align__(8) uint64_t s_empty[4];
    __shared__ __align__(8) uint64_t s_done;
    __shared__ uint32_t s_tptr;

    uint32_t sbase = (smem_u32(dyn) + 1023u) & ~1023u;
    uint32_t fullb  = smem_u32(&s_full[0]);
    uint32_t emptyb = smem_u32(&s_empty[0]);
    uint32_t dn     = smem_u32(&s_done);

    if (wid == 0) T5_ALLOC(smem_u32(&s_tptr), 512);
    if (tid == 0) {
#pragma unroll
        for (int m = 0; m < 4; m++) {
            MBAR_INIT(fullb + m * 8, 1);
            MBAR_INIT(emptyb + m * 8, 1);
        }
        MBAR_INIT(dn, 1);
    }
    __syncthreads();
    uint32_t tmem;
    asm volatile("ld.shared.b32 %0, [%1];" : "=r"(tmem) : "r"(smem_u32(&s_tptr)));

    const __nv_bfloat16* Whh0t = g_Whh0b + (size_t)bid * 131072;
    const __nv_bfloat16* Wih1t = g_Wih1b + (size_t)bid * 131072;
    const __nv_bfloat16* Whh1t = g_Whh1b + (size_t)bid * 131072;
    const uint32_t bhi = (uint32_t)(bid >> 2) * 16384u;           // h hi-block
    const uint32_t blo = bhi + 16u * 16384u;                      // h lo-block
    const uint32_t ib0 = (uint32_t)(bid & 3) * 16u;               // inner col

    int gctr = 0, ph = 0;
    uint32_t dd[64];

    for (int t = 0; t < SEQ; t++) {
        const int p = t & 1;

        // ---- Phase A: gates0 = h0[p] @ Whh0'^T  (+gates_x in epilogue) ----
        do_phase_t5(16, g_h0b[p], Whh0t, g_h0b[p], Whh0t,
                    sbase, tmem, fullb, emptyb, dn, gctr, ph, dd, tid);
        {
            const float* gx = g_gates_x + ((size_t)(t * BATCH + tid)) * G4 + n0;
            uint8_t* hb = (uint8_t*)g_h0b[p ^ 1];
#pragma unroll
            for (int jj = 0; jj < 16; jj++) {
                float iv = sigf (__uint_as_float(dd[jj])      + gx[jj]);
                float fv = sigf (__uint_as_float(dd[16 + jj]) + gx[16 + jj]);
                float gv = tanhf(__uint_as_float(dd[32 + jj]) + gx[32 + jj]);
                float ov = sigf (__uint_as_float(dd[48 + jj]) + gx[48 + jj]);
                float cn = fv * c0[jj] + iv * gv;
                c0[jj] = cn;
                float h = ov * tanhf(cn);
                __nv_bfloat16 hi = __float2bfloat16(h);
                __nv_bfloat16 lo = __float2bfloat16(h - __bfloat162float(hi));
                uint32_t off = (uint32_t)tid * 128u + ((ib0 + jj) << 1);
                uint32_t soff = off ^ ((off >> 3) & 0x70);
                *(__nv_bfloat16*)(hb + bhi + soff) = hi;
                *(__nv_bfloat16*)(hb + blo + soff) = lo;
            }
        }
        grid_bar();

        // ---- Phase B: gates1 = h0[p^1]@Wih1'^T + h1[p]@Whh1'^T + bias1 ----
        do_phase_t5(32, g_h0b[p ^ 1], Wih1t, g_h1b[p], Whh1t,
                    sbase, tmem, fullb, emptyb, dn, gctr, ph, dd, tid);
        {
            const float* bs = g_bias1 + n0;
            uint8_t* hb = (uint8_t*)g_h1b[p ^ 1];
            float* op = out + ((size_t)tid * SEQ + t) * HDIM + j0;
#pragma unroll
            for (int jj = 0; jj < 16; jj++) {
                float iv = sigf (__uint_as_float(dd[jj])      + bs[jj]);
                float fv = sigf (__uint_as_float(dd[16 + jj]) + bs[16 + jj]);
                float gv = tanhf(__uint_as_float(dd[32 + jj]) + bs[32 + jj]);
                float ov = sigf (__uint_as_float(dd[48 + jj]) + bs[48 + jj]);
                float cn = fv * c1[jj] + iv * gv;
                c1[jj] = cn;
                float h = ov * tanhf(cn);
                __nv_bfloat16 hi = __float2bfloat16(h);
                __nv_bfloat16 lo = __float2bfloat16(h - __bfloat162float(hi));
                uint32_t off = (uint32_t)tid * 128u + ((ib0 + jj) << 1);
                uint32_t soff = off ^ ((off >> 3) & 0x70);
                *(__nv_bfloat16*)(hb + bhi + soff) = hi;
                *(__nv_bfloat16*)(hb + blo + soff) = lo;
                op[jj] = h;
            }
        }
        __syncthreads();   // all warps done with TMEM/epilogue before next phase
    }

    __syncthreads();
    if (wid == 0) { T5_RELINQ(); T5_DEALLOC(tmem, 512); }

#else
    // =============== mma.sync fallback (non-'a' target pass) ===============
    __nv_bfloat16* sA = (__nv_bfloat16*)dyn;
    __nv_bfloat16* sB = sA + 4 * 128 * SSTR;
    float* sAcc = (float*)dyn;
    const int lane = tid & 31, warp = tid >> 5;
    const int wm = warp & 1, wn = warp >> 1;

    float acc[64];

    auto epi_to_smem = [&]() {
        __syncthreads();
#pragma unroll
        for (int mi = 0; mi < 4; mi++)
#pragma unroll
            for (int ng = 0; ng < 2; ng++)
#pragma unroll
                for (int hf = 0; hf < 2; hf++) {
                    const float* a4 = acc + ((mi * 4) + 2 * ng + hf) * 4;
                    int r = wm * 64 + mi * 16 + (lane >> 2);
                    int c = wn * 32 + ng * 16 + hf * 8 + ((lane & 3) << 1);
                    sAcc[r * 68 + c]           = a4[0];
                    sAcc[r * 68 + c + 1]       = a4[1];
                    sAcc[(r + 8) * 68 + c]     = a4[2];
                    sAcc[(r + 8) * 68 + c + 1] = a4[3];
                }
        __syncthreads();
    };

    for (int t = 0; t < SEQ; t++) {
        const int p = t & 1;

#pragma unroll
        for (int i = 0; i < 64; i++) acc[i] = 0.0f;
        gemm_cp<128, 64, 2, 2, 128>(g_h0s[p], g_Whh0s + (size_t)n0 * KS, acc, sA, sB);
        epi_to_smem();
        {
            const float* gx = g_gates_x + ((size_t)(t * BATCH + tid)) * G4 + n0;
            const float* ga = sAcc + tid * 68;
            __nv_bfloat16* hb = g_h0s[p ^ 1] + (size_t)tid * KS + j0;
#pragma unroll
            for (int jj = 0; jj < 16; jj++) {
                float iv = sigf (ga[jj]      + gx[jj]);
                float fv = sigf (ga[16 + jj] + gx[16 + jj]);
                float gv = tanhf(ga[32 + jj] + gx[32 + jj]);
                float ov = sigf (ga[48 + jj] + gx[48 + jj]);
                float cn = fv * c0[jj] + iv * gv;
                c0[jj] = cn;
                float h = ov * tanhf(cn);
                __nv_bfloat16 hi = __float2bfloat16(h);
                hb[jj]        = hi;
                hb[1024 + jj] = __float2bfloat16(h - __bfloat162float(hi));
            }
        }
        grid_bar();

#pragma unroll
        for (int i = 0; i < 64; i++) acc[i] = 0.0f;
        gemm_cp<128, 64, 2, 2, 128>(g_h0s[p ^ 1], g_Wih1s + (size_t)n0 * KS, acc, sA, sB);
        gemm_cp<128, 64, 2, 2, 128>(g_h1s[p], g_Whh1s + (size_t)n0 * KS, acc, sA, sB);
        epi_to_smem();
        {
            const float* bs = g_bias1 + n0;
            const float* ga = sAcc + tid * 68;
            __nv_bfloat16* hb = g_h1s[p ^ 1] + (size_t)tid * KS + j0;
            float* op = out + ((size_t)tid * SEQ + t) * HDIM + j0;
#pragma unroll
            for (int jj = 0; jj < 16; jj++) {
                float iv = sigf (ga[jj]      + bs[jj]);
                float fv = sigf (ga[16 + jj] + bs[16 + jj]);
                float gv = tanhf(ga[32 + jj] + bs[32 + jj]);
                float ov = sigf (ga[48 + jj] + bs[48 + jj]);
                float cn = fv * c1[jj] + iv * gv;
                c1[jj] = cn;
                float h = ov * tanhf(cn);
                __nv_bfloat16 hi = __float2bfloat16(h);
                hb[jj]        = hi;
                hb[1024 + jj] = __float2bfloat16(h - __bfloat162float(hi));
                op[jj] = h;
            }
        }
        __syncthreads();
    }
#endif
}

// -------------------------------- launcher ----------------------------------
extern "C" void kernel_launch(void* const* d_in, const int* in_sizes, int n_in,
                              void* d_out, int out_size) {
    const float* x     = (const float*)d_in[0];
    const float* W_ih0 = (const float*)d_in[1];
    const float* b_ih0 = (const float*)d_in[2];
    const float* W_hh0 = (const float*)d_in[3];
    const float* b_hh0 = (const float*)d_in[4];
    const float* W_ih1 = (const float*)d_in[5];
    const float* b_ih1 = (const float*)d_in[6];
    const float* W_hh1 = (const float*)d_in[7];
    const float* b_hh1 = (const float*)d_in[8];
    float* out = (float*)d_out;

    cudaFuncSetAttribute(k_gemm_pre, cudaFuncAttributeMaxDynamicSharedMemorySize, PRE_SMEM);
    cudaFuncSetAttribute(k_scan,     cudaFuncAttributeMaxDynamicSharedMemorySize, SCAN_DYN);

    // prep (2 launches -- 4 total so the fixed ncu window hits k_scan)
    k_prep_w<<<(4 * G4 * FDIM + 255) / 256, 256>>>(W_ih0, W_hh0, W_ih1, W_hh1,
                                                   b_ih0, b_hh0, b_ih1, b_hh1);
    k_prep_x<<<(MTOT * FDIM + 255) / 256, 256>>>(x);

    // input-projection GEMM for all timesteps
    k_gemm_pre<<<dim3(G4 / 128, MTOT / 128), 256, PRE_SMEM>>>();

    // persistent scan (tcgen05+TMA on arch-specific cubin, mma.sync otherwise)
    k_scan<<<NCTA, 128, SCAN_DYN>>>(out);
}